// round 2
// baseline (speedup 1.0000x reference)
#include <cuda_runtime.h>
#include <stdint.h>

// RVAEModel: out[b, c, g] = weight[idx[b, g], c]
//   idx:    [256, 64]  (int32 OR int64 — detected at runtime)
//   weight: fp32 [1024, 1024]
//   out:    fp32 [256, 1024, 8, 8] (= [256, 1024, 64])
//
// Shared-memory transpose tile per (b, 64-wide c-tile):
//   phase 1: coalesced float4 gather of 64 weight rows x 64 cols -> smem
//   phase 2: coalesced float4 writes along g (fast output dim)

static constexpr int BS = 256;
static constexpr int M  = 64;    // tokens per sample (g)
static constexpr int C  = 1024;  // channels
static constexpr int TC = 64;    // c-tile width
static constexpr int PITCH = 65; // smem row pitch (floats)

__device__ int g_idx_is64; // 1 if indices buffer is int64, 0 if int32

// Indices are in [0, 1024). If the buffer is little-endian int64, the odd
// 32-bit words of the first 64 indices are all zero. If int32, the first
// 128 words are 128 random indices in [0,1024) — all-64-odd-words-zero has
// probability (1/1024)^64 ~ 0. Reads only 128 words: in-bounds either way.
__global__ void detect_idx_dtype(const unsigned int* __restrict__ idx_words)
{
    unsigned int acc = 0;
    #pragma unroll
    for (int i = 0; i < 64; i++) acc |= idx_words[2 * i + 1];
    g_idx_is64 = (acc == 0) ? 1 : 0;
}

__global__ __launch_bounds__(256, 8)
void rvae_gather_transpose(const void*  __restrict__ idx_raw,
                           const float* __restrict__ w,
                           float*       __restrict__ out)
{
    const int b  = blockIdx.y;
    const int c0 = blockIdx.x * TC;
    const int t  = threadIdx.x; // 256 threads

    __shared__ int   rows[M];
    __shared__ float tile[M * PITCH]; // tile[g*PITCH + c_local]

    if (t < M) {
        if (g_idx_is64)
            rows[t] = (int)((const long long*)idx_raw)[(size_t)b * M + t];
        else
            rows[t] = ((const int*)idx_raw)[(size_t)b * M + t];
    }
    __syncthreads();

    // ---- Phase 1: load weight rows (coalesced float4 along c) ----
    // 64 g-rows x 16 float4-cols = 1024 slots; 256 threads x 4 iters.
    #pragma unroll
    for (int i = 0; i < 4; i++) {
        const int slot = t + i * 256;
        const int g    = slot >> 4;   // 0..63
        const int c4   = slot & 15;   // 0..15
        const float4 v = *reinterpret_cast<const float4*>(
            w + (size_t)rows[g] * C + c0 + (c4 << 2));
        float* dst = &tile[g * PITCH + (c4 << 2)];
        dst[0] = v.x; dst[1] = v.y; dst[2] = v.z; dst[3] = v.w;
    }
    __syncthreads();

    // ---- Phase 2: write out[b, c0+cl, g] (coalesced float4 along g) ----
    float* ob = out + (size_t)b * (C * M) + (size_t)c0 * M;
    #pragma unroll
    for (int i = 0; i < 4; i++) {
        const int slot = t + i * 256;
        const int cl   = slot >> 4;        // 0..63 (local channel)
        const int gb   = (slot & 15) << 2; // 0,4,...,60
        float4 v;
        v.x = tile[(gb + 0) * PITCH + cl];
        v.y = tile[(gb + 1) * PITCH + cl];
        v.z = tile[(gb + 2) * PITCH + cl];
        v.w = tile[(gb + 3) * PITCH + cl];
        *reinterpret_cast<float4*>(ob + cl * M + gb) = v;
    }
}

extern "C" void kernel_launch(void* const* d_in, const int* in_sizes, int n_in,
                              void* d_out, int out_size)
{
    // Identify inputs by element count:
    //   indices: 256*64 = 16384 elements
    //   weight:  1024*1024 = 1048576 elements (fp32)
    const void*  idx;
    const float* w;
    if (in_sizes[0] == BS * M) {
        idx = d_in[0];
        w   = (const float*)d_in[1];
    } else {
        idx = d_in[1];
        w   = (const float*)d_in[0];
    }

    detect_idx_dtype<<<1, 1>>>((const unsigned int*)idx);

    dim3 grid(C / TC, BS); // (16, 256)
    rvae_gather_transpose<<<grid, 256>>>(idx, w, (float*)d_out);
}

// round 3
// speedup vs baseline: 1.0977x; 1.0977x over previous
#include <cuda_runtime.h>
#include <stdint.h>

// RVAEModel: out[b, c, g] = weight[idx[b, g], c]
//   idx:    [256, 64]  (int32 OR int64 — detected at runtime)
//   weight: fp32 [1024, 1024]
//   out:    fp32 [256, 1024, 8, 8] (= [256, 1024, 64])
//
// Per-block (b, 64-wide c-tile) transpose with all-128-bit traffic:
//   phase 1: 4x LDG.128 (coalesced) -> 4x STS.128 into XOR-swizzled tile
//   phase 2: 4x LDS.128 (conflict-free) -> register 4x4 transpose -> 4x STG.128
// Tile: 64 g-rows x 16 float4 cols, physical col = c4 ^ (g>>2).

static constexpr int BS = 256;
static constexpr int M  = 64;    // tokens per sample (g)
static constexpr int C  = 1024;  // channels
static constexpr int TC = 64;    // c-tile width

__device__ int g_idx_is64; // 1 if indices buffer is int64, 0 if int32

// Indices are in [0, 1024). If buffer is little-endian int64, odd 32-bit
// words of the first 64 indices are all zero; for int32 data the chance of
// that is (1/1024)^64 ~ 0. Reads 128 words — in-bounds either way.
__global__ void detect_idx_dtype(const unsigned int* __restrict__ idx_words)
{
    unsigned int acc = 0;
    #pragma unroll
    for (int i = 0; i < 64; i++) acc |= idx_words[2 * i + 1];
    g_idx_is64 = (acc == 0) ? 1 : 0;
}

__global__ __launch_bounds__(256, 8)
void rvae_gather_transpose(const void*  __restrict__ idx_raw,
                           const float* __restrict__ w,
                           float*       __restrict__ out)
{
    const int b  = blockIdx.y;
    const int c0 = blockIdx.x * TC;
    const int t  = threadIdx.x; // 256 threads

    __shared__ int    rows[M];
    __shared__ float4 tile[M * 16]; // tile[g*16 + (c4 ^ (g>>2))] = weight[rows[g], c0+4*c4 ..]

    if (t < M) {
        if (g_idx_is64)
            rows[t] = (int)((const long long*)idx_raw)[(size_t)b * M + t];
        else
            rows[t] = ((const int*)idx_raw)[(size_t)b * M + t];
    }
    __syncthreads();

    // ---- Phase 1: gather 64 rows x 64 cols (all 128-bit, conflict-free) ----
    #pragma unroll
    for (int i = 0; i < 4; i++) {
        const int slot = t + i * 256;
        const int g    = slot >> 4;   // 0..63
        const int c4   = slot & 15;   // 0..15 (float4 column)
        const float4 v = *reinterpret_cast<const float4*>(
            w + (size_t)rows[g] * C + c0 + (c4 << 2));
        tile[g * 16 + (c4 ^ (g >> 2))] = v;
    }
    __syncthreads();

    // ---- Phase 2: 4x4 register transpose + coalesced 128-bit stores ----
    const int br = t & 15;  // g-block: g = 4*br + k
    const int bc = t >> 4;  // c-block: c = c0 + 4*bc + j
    const int sc = bc ^ br; // swizzled physical column

    const float4 r0 = tile[(4 * br + 0) * 16 + sc];
    const float4 r1 = tile[(4 * br + 1) * 16 + sc];
    const float4 r2 = tile[(4 * br + 2) * 16 + sc];
    const float4 r3 = tile[(4 * br + 3) * 16 + sc];

    float* ob = out + (size_t)b * (C * M) + (size_t)c0 * M + 4 * br;
    const float4 o0 = {r0.x, r1.x, r2.x, r3.x};
    const float4 o1 = {r0.y, r1.y, r2.y, r3.y};
    const float4 o2 = {r0.z, r1.z, r2.z, r3.z};
    const float4 o3 = {r0.w, r1.w, r2.w, r3.w};
    *reinterpret_cast<float4*>(ob + (4 * bc + 0) * M) = o0;
    *reinterpret_cast<float4*>(ob + (4 * bc + 1) * M) = o1;
    *reinterpret_cast<float4*>(ob + (4 * bc + 2) * M) = o2;
    *reinterpret_cast<float4*>(ob + (4 * bc + 3) * M) = o3;
}

extern "C" void kernel_launch(void* const* d_in, const int* in_sizes, int n_in,
                              void* d_out, int out_size)
{
    // indices: 16384 elements; weight: 1048576 elements (fp32)
    const void*  idx;
    const float* w;
    if (in_sizes[0] == BS * M) {
        idx = d_in[0];
        w   = (const float*)d_in[1];
    } else {
        idx = d_in[1];
        w   = (const float*)d_in[0];
    }

    detect_idx_dtype<<<1, 1>>>((const unsigned int*)idx);

    dim3 grid(C / TC, BS); // (16, 256)
    rvae_gather_transpose<<<grid, 256>>>(idx, w, (float*)d_out);
}

// round 4
// speedup vs baseline: 1.2703x; 1.1572x over previous
#include <cuda_runtime.h>
#include <stdint.h>

// RVAEModel: out[b, c, g] = weight[idx[b, g], c]
//   idx:    [256, 64]  (int32 OR int64 — detected at runtime)
//   weight: fp32 [1024, 1024]
//   out:    fp32 [256, 1024, 8, 8] (= [256, 1024, 64])
//
// Per-block (b, 128-wide c-tile), two 64-col subtiles, software-pipelined:
//   cp.async gather subtile0, subtile1 (separate commit groups)
//   wait_group 1 -> transpose+store subtile0 (overlaps subtile1 loads)
//   wait_group 0 -> transpose+store subtile1
// Each subtile: 64 g x 16 float4, XOR swizzle col = c4 ^ (g>>2);
// all smem traffic 128-bit conflict-free, all global 128-bit coalesced.

static constexpr int BS = 256;
static constexpr int M  = 64;    // tokens per sample (g)
static constexpr int C  = 1024;  // channels
static constexpr int TC = 128;   // c-tile width per block

__device__ int g_idx_is64; // 1 if indices buffer is int64, 0 if int32

// Indices are in [0, 1024). If buffer is little-endian int64, odd 32-bit
// words of the first 64 indices are all zero; for int32 data that has
// probability (1/1024)^64 ~ 0. Reads 128 words — in-bounds either way.
__global__ void detect_idx_dtype(const unsigned int* __restrict__ idx_words)
{
    unsigned int acc = 0;
    #pragma unroll
    for (int i = 0; i < 64; i++) acc |= idx_words[2 * i + 1];
    g_idx_is64 = (acc == 0) ? 1 : 0;
}

__global__ __launch_bounds__(256, 7)
void rvae_gather_transpose(const void*  __restrict__ idx_raw,
                           const float* __restrict__ w,
                           float*       __restrict__ out)
{
    const int b  = blockIdx.y;
    const int c0 = blockIdx.x * TC;
    const int t  = threadIdx.x; // 256 threads

    __shared__ int    rows[M];
    __shared__ float4 tile[2][M * 16]; // [h][g*16 + (c4 ^ (g>>2))]

    if (t < M) {
        if (g_idx_is64)
            rows[t] = (int)((const long long*)idx_raw)[(size_t)b * M + t];
        else
            rows[t] = ((const int*)idx_raw)[(size_t)b * M + t];
    }
    __syncthreads();

    // ---- Phase 1: async gather of both subtiles ----
    #pragma unroll
    for (int h = 0; h < 2; h++) {
        #pragma unroll
        for (int i = 0; i < 4; i++) {
            const int slot = t + i * 256;
            const int g    = slot >> 4;   // 0..63
            const int c4   = slot & 15;   // 0..15 (float4 column)
            const float* src = w + (size_t)rows[g] * C + c0 + h * 64 + (c4 << 2);
            const uint32_t dst = (uint32_t)__cvta_generic_to_shared(
                &tile[h][g * 16 + (c4 ^ (g >> 2))]);
            asm volatile("cp.async.cg.shared.global [%0], [%1], 16;"
                         :: "r"(dst), "l"(src) : "memory");
        }
        asm volatile("cp.async.commit_group;" ::: "memory");
    }

    // ---- Phase 2: pipelined transpose + store ----
    const int br = t & 15;  // g-block: g = 4*br + k
    const int bc = t >> 4;  // c-block within subtile: c = 4*bc + j
    const int sc = bc ^ br; // swizzled physical column
    float* ob = out + (size_t)b * (C * M) + (size_t)c0 * M + 4 * br;

    asm volatile("cp.async.wait_group 1;" ::: "memory");
    __syncthreads(); // subtile 0 complete for all threads

    #pragma unroll
    for (int h = 0; h < 2; h++) {
        if (h == 1) {
            asm volatile("cp.async.wait_group 0;" ::: "memory");
            __syncthreads(); // subtile 1 complete for all threads
        }
        const float4 r0 = tile[h][(4 * br + 0) * 16 + sc];
        const float4 r1 = tile[h][(4 * br + 1) * 16 + sc];
        const float4 r2 = tile[h][(4 * br + 2) * 16 + sc];
        const float4 r3 = tile[h][(4 * br + 3) * 16 + sc];

        const float4 o0 = {r0.x, r1.x, r2.x, r3.x};
        const float4 o1 = {r0.y, r1.y, r2.y, r3.y};
        const float4 o2 = {r0.z, r1.z, r2.z, r3.z};
        const float4 o3 = {r0.w, r1.w, r2.w, r3.w};
        float* oh = ob + (size_t)(h * 64) * M;
        *reinterpret_cast<float4*>(oh + (4 * bc + 0) * M) = o0;
        *reinterpret_cast<float4*>(oh + (4 * bc + 1) * M) = o1;
        *reinterpret_cast<float4*>(oh + (4 * bc + 2) * M) = o2;
        *reinterpret_cast<float4*>(oh + (4 * bc + 3) * M) = o3;
    }
}

extern "C" void kernel_launch(void* const* d_in, const int* in_sizes, int n_in,
                              void* d_out, int out_size)
{
    // indices: 16384 elements; weight: 1048576 elements (fp32)
    const void*  idx;
    const float* w;
    if (in_sizes[0] == BS * M) {
        idx = d_in[0];
        w   = (const float*)d_in[1];
    } else {
        idx = d_in[1];
        w   = (const float*)d_in[0];
    }

    detect_idx_dtype<<<1, 1>>>((const unsigned int*)idx);

    dim3 grid(C / TC, BS); // (8, 256)
    rvae_gather_transpose<<<grid, 256>>>(idx, w, (float*)d_out);
}